// round 11
// baseline (speedup 1.0000x reference)
#include <cuda_runtime.h>
#include <cstdint>

// T=8192, B=512, H=16, IN=1, OUT=5; output = FC(GRU hidden of batch index 511).
#define T_LEN 8192
#define BATCH 512
#define HID   16
#define NOUT  5
#define NCHUNK (T_LEN / 32)

// Transposed history: g_hist[j * T_LEN + t]
__device__ float g_hist[HID * T_LEN];

__device__ __forceinline__ float tanhap(float x) {
    float y; asm("tanh.approx.f32 %0, %1;" : "=f"(y) : "f"(x)); return y;
}
__device__ __forceinline__ unsigned long long pk2(float lo, float hi) {
    unsigned long long r; asm("mov.b64 %0, {%1, %2};" : "=l"(r) : "f"(lo), "f"(hi)); return r;
}
__device__ __forceinline__ void upk2(float& lo, float& hi, unsigned long long v) {
    asm("mov.b64 {%0, %1}, %2;" : "=f"(lo), "=f"(hi) : "l"(v));
}
__device__ __forceinline__ unsigned long long fma2(unsigned long long a, unsigned long long b,
                                                   unsigned long long c) {
    unsigned long long d;
    asm("fma.rn.f32x2 %0, %1, %2, %3;" : "=l"(d) : "l"(a), "l"(b), "l"(c));
    return d;
}
__device__ __forceinline__ unsigned long long add2(unsigned long long a, unsigned long long b) {
    unsigned long long d;
    asm("add.rn.f32x2 %0, %1, %2;" : "=l"(d) : "l"(a), "l"(b));
    return d;
}
__device__ __forceinline__ uint32_t smem_u32(const void* p) {
    uint32_t a;
    asm("{ .reg .u64 t; cvta.to.shared.u64 t, %1; cvt.u32.u64 %0, t; }" : "=r"(a) : "l"(p));
    return a;
}

__global__ void __launch_bounds__(64, 1)
gru_seq_kernel(const float* __restrict__ x,
               const float* __restrict__ w_ih,
               const float* __restrict__ w_hh,
               const float* __restrict__ b_ih,
               const float* __restrict__ b_hh)
{
    __shared__ __align__(16) float hbuf[16];
    // Double-buffered x-gate seeds. Per step s, per unit j:
    //   xgbuf[buf][s][j] = (xgr, 0, xgz, 0)  -> one LDS.128 = both packed seeds
    //   xnbuf[buf][s][j] = xgn
    __shared__ __align__(16) float xgbuf[2 * 32 * 16 * 4];   // 16 KB
    __shared__ __align__(16) float xnbuf[2 * 32 * 16];       //  4 KB

    const int tid  = threadIdx.x;
    const int wid  = tid >> 5;
    const int lane = tid & 31;
    const int j    = lane & 15;

    if (wid == 1) {
        // ---------------- helper warp: precompute x-gate seeds ----------------
        const int s = lane;   // one timestep of the chunk per lane
        float wri[16], wzi[16], wni[16], brr[16], bzz[16], bnn[16];
        #pragma unroll
        for (int k = 0; k < 16; ++k) {
            wri[k] = 0.5f * w_ih[k];
            brr[k] = 0.5f * (b_ih[k] + b_hh[k]);
            wzi[k] = 0.5f * w_ih[HID + k];
            bzz[k] = 0.5f * (b_ih[HID + k] + b_hh[HID + k]);
            wni[k] = w_ih[2 * HID + k];
            bnn[k] = b_ih[2 * HID + k];
        }
        // fill buffer 0 with chunk 0
        {
            const float xt = x[s * BATCH + (BATCH - 1)];
            float4* xg = (float4*)&xgbuf[(0 * 32 + s) * 64];
            float*  xn = &xnbuf[(0 * 32 + s) * 16];
            #pragma unroll
            for (int k = 0; k < 16; ++k) {
                xg[k] = make_float4(fmaf(xt, wri[k], brr[k]), 0.0f,
                                    fmaf(xt, wzi[k], bzz[k]), 0.0f);
                xn[k] = fmaf(xt, wni[k], bnn[k]);
            }
        }
        __syncthreads();                       // buffer 0 ready
        for (int c = 0; c < NCHUNK; ++c) {
            if (c + 1 < NCHUNK) {
                const float xt = x[((c + 1) * 32 + s) * BATCH + (BATCH - 1)];
                const int b = (c + 1) & 1;
                float4* xg = (float4*)&xgbuf[(b * 32 + s) * 64];
                float*  xn = &xnbuf[(b * 32 + s) * 16];
                #pragma unroll
                for (int k = 0; k < 16; ++k) {
                    xg[k] = make_float4(fmaf(xt, wri[k], brr[k]), 0.0f,
                                        fmaf(xt, wzi[k], bzz[k]), 0.0f);
                    xn[k] = fmaf(xt, wni[k], bnn[k]);
                }
            }
            __syncthreads();                   // chunk c consumed / c+1 ready
        }
        return;
    }

    // ---------------- main warp: the serial recurrence ----------------
    // sigmoid(v) = 0.5 + 0.5*tanh(v/2): r/z rows pre-halved.
    // n: narg = xgn + D + t_r*D with D = 0.5*(w_n.h + b_n).
    unsigned long long wr[8], wz[8], wn[8];
    #pragma unroll
    for (int k = 0; k < 8; ++k) {
        const float* rr = &w_hh[j * HID];
        const float* rz = &w_hh[(HID + j) * HID];
        const float* rn = &w_hh[(2 * HID + j) * HID];
        wr[k] = pk2(0.5f * rr[2 * k], 0.5f * rr[2 * k + 1]);
        wz[k] = pk2(0.5f * rz[2 * k], 0.5f * rz[2 * k + 1]);
        wn[k] = pk2(0.5f * rn[2 * k], 0.5f * rn[2 * k + 1]);
    }
    const unsigned long long bn2pk = pk2(0.5f * b_hh[2 * HID + j], 0.0f);
    const unsigned long long Z64 = 0ull;

    if (lane < 16) hbuf[j] = 0.0f;
    __syncwarp();
    float h_own = 0.0f;

    const uint32_t sbase = smem_u32(&hbuf[0]);
    const uint32_t waddr = sbase + (uint32_t)(j * 4);
    uint32_t xg_base = smem_u32(&xgbuf[0]) + (uint32_t)(j * 16);
    uint32_t xn_base = smem_u32(&xnbuf[0]) + (uint32_t)(j * 4);

    float4* histp = (float4*)&g_hist[j * T_LEN];
    float4 hacc;

    __syncthreads();                           // wait for buffer 0

    for (int c = 0; c < NCHUNK; ++c) {
        #pragma unroll
        for (int s = 0; s < 32; ++s) {
            // warp-synchronous single-buffer roundtrip (in-order smem pipeline)
            unsigned long long h0, h1, h2, h3, h4, h5, h6, h7;
            asm volatile("ld.shared.v2.u64 {%0, %1}, [%2];" : "=l"(h0), "=l"(h1) : "r"(sbase));
            asm volatile("ld.shared.v2.u64 {%0, %1}, [%2];" : "=l"(h2), "=l"(h3) : "r"(sbase + 16));
            asm volatile("ld.shared.v2.u64 {%0, %1}, [%2];" : "=l"(h4), "=l"(h5) : "r"(sbase + 32));
            asm volatile("ld.shared.v2.u64 {%0, %1}, [%2];" : "=l"(h6), "=l"(h7) : "r"(sbase + 48));

            // precomputed seeds: one LDS.128 -> (xgr,0) and (xgz,0); one LDS.32 -> xgn
            unsigned long long seed_r, seed_z;
            asm volatile("ld.shared.v2.u64 {%0, %1}, [%2];"
                         : "=l"(seed_r), "=l"(seed_z) : "r"(xg_base + (uint32_t)(s * 256)));
            float xgn;
            asm volatile("ld.shared.f32 %0, [%1];"
                         : "=f"(xgn) : "r"(xn_base + (uint32_t)(s * 64)));

            unsigned long long ar0, ar1, az0, az1, an0, an1;
            ar0 = fma2(wr[0], h0, seed_r); ar1 = fma2(wr[1], h1, Z64);
            an0 = fma2(wn[0], h0, bn2pk);  an1 = fma2(wn[1], h1, Z64);
            az0 = fma2(wz[0], h0, seed_z); az1 = fma2(wz[1], h1, Z64);
            ar0 = fma2(wr[2], h2, ar0);    ar1 = fma2(wr[3], h3, ar1);
            an0 = fma2(wn[2], h2, an0);    an1 = fma2(wn[3], h3, an1);
            az0 = fma2(wz[2], h2, az0);    az1 = fma2(wz[3], h3, az1);
            ar0 = fma2(wr[4], h4, ar0);    ar1 = fma2(wr[5], h5, ar1);
            an0 = fma2(wn[4], h4, an0);    an1 = fma2(wn[5], h5, an1);
            az0 = fma2(wz[4], h4, az0);    az1 = fma2(wz[5], h5, az1);
            ar0 = fma2(wr[6], h6, ar0);    ar1 = fma2(wr[7], h7, ar1);
            an0 = fma2(wn[6], h6, an0);    an1 = fma2(wn[7], h7, an1);
            az0 = fma2(wz[6], h6, az0);    az1 = fma2(wz[7], h7, az1);

            float lo, hi;
            upk2(lo, hi, add2(ar0, ar1)); const float gr = lo + hi;   // includes xgr
            upk2(lo, hi, add2(an0, an1)); const float D  = lo + hi;   // 0.5*(w_n.h+b_n)
            upk2(lo, hi, add2(az0, az1)); const float gz = lo + hi;   // includes xgz

            const float t_r = tanhap(gr);
            const float t_z = tanhap(gz);
            const float xnD = xgn + D;                 // hidden under t_r MUFU
            const float zg  = fmaf(0.5f, t_z, 0.5f);
            const float omz = fmaf(-0.5f, t_z, 0.5f);
            const float zh  = zg * h_own;

            const float narg = fmaf(t_r, D, xnD);
            const float n    = tanhap(narg);
            const float hn   = fmaf(n, omz, zh);       // single FMA after tanh_n
            h_own = hn;

            asm volatile("st.shared.f32 [%0], %1;" :: "r"(waddr), "f"(hn));

            // batched history write (one STG.128 per 4 steps)
            if ((s & 3) == 0) hacc.x = hn;
            else if ((s & 3) == 1) hacc.y = hn;
            else if ((s & 3) == 2) hacc.z = hn;
            else { hacc.w = hn; *histp = hacc; ++histp; }
        }
        xg_base ^= (uint32_t)(32 * 16 * 16);   // toggle 16 KB buffer half
        xn_base ^= (uint32_t)(32 * 16 * 4);    // toggle 4 KB buffer half
        __syncthreads();                       // release chunk c, acquire c+1
    }
}

// out[t][o] = h_t . fc_w[o] + fc_b[o]   (history is [k][t] transposed)
__global__ void fc_kernel(const float* __restrict__ fc_w,
                          const float* __restrict__ fc_b,
                          float* __restrict__ out)
{
    const int i = blockIdx.x * blockDim.x + threadIdx.x;
    if (i >= T_LEN * NOUT) return;
    const int t = i / NOUT;
    const int o = i - t * NOUT;
    float acc = fc_b[o];
    #pragma unroll
    for (int k = 0; k < HID; ++k)
        acc = fmaf(g_hist[k * T_LEN + t], fc_w[o * HID + k], acc);
    out[i] = acc;
}

extern "C" void kernel_launch(void* const* d_in, const int* in_sizes, int n_in,
                              void* d_out, int out_size)
{
    const float* x    = (const float*)d_in[0];
    const float* w_ih = (const float*)d_in[1];
    const float* w_hh = (const float*)d_in[2];
    const float* b_ih = (const float*)d_in[3];
    const float* b_hh = (const float*)d_in[4];
    const float* fc_w = (const float*)d_in[5];
    const float* fc_b = (const float*)d_in[6];
    float* out = (float*)d_out;

    gru_seq_kernel<<<1, 64>>>(x, w_ih, w_hh, b_ih, b_hh);

    const int n = T_LEN * NOUT;
    fc_kernel<<<(n + 255) / 256, 256>>>(fc_w, fc_b, out);
}

// round 12
// speedup vs baseline: 1.1415x; 1.1415x over previous
#include <cuda_runtime.h>
#include <cstdint>

// T=8192, B=512, H=16, IN=1, OUT=5; output = FC(GRU hidden of batch index 511).
#define T_LEN 8192
#define BATCH 512
#define HID   16
#define NOUT  5
#define NCHUNK (T_LEN / 32)

// Transposed history with one private row per LANE (rows 16..31 are unused
// duplicates written by the redundant half-warp; fc reads rows 0..15 only).
__device__ float g_hist[32 * T_LEN];

__device__ __forceinline__ float tanhap(float x) {
    float y; asm("tanh.approx.f32 %0, %1;" : "=f"(y) : "f"(x)); return y;
}
__device__ __forceinline__ unsigned long long pk2(float lo, float hi) {
    unsigned long long r; asm("mov.b64 %0, {%1, %2};" : "=l"(r) : "f"(lo), "f"(hi)); return r;
}
__device__ __forceinline__ void upk2(float& lo, float& hi, unsigned long long v) {
    asm("mov.b64 {%0, %1}, %2;" : "=f"(lo), "=f"(hi) : "l"(v));
}
__device__ __forceinline__ unsigned long long fma2(unsigned long long a, unsigned long long b,
                                                   unsigned long long c) {
    unsigned long long d;
    asm("fma.rn.f32x2 %0, %1, %2, %3;" : "=l"(d) : "l"(a), "l"(b), "l"(c));
    return d;
}
__device__ __forceinline__ unsigned long long add2(unsigned long long a, unsigned long long b) {
    unsigned long long d;
    asm("add.rn.f32x2 %0, %1, %2;" : "=l"(d) : "l"(a), "l"(b));
    return d;
}
__device__ __forceinline__ uint32_t smem_u32(const void* p) {
    uint32_t a;
    asm("{ .reg .u64 t; cvta.to.shared.u64 t, %1; cvt.u32.u64 %0, t; }" : "=r"(a) : "l"(p));
    return a;
}

__global__ void __launch_bounds__(32, 1)
gru_seq_kernel(const float* __restrict__ x,
               const float* __restrict__ w_ih,
               const float* __restrict__ w_hh,
               const float* __restrict__ b_ih,
               const float* __restrict__ b_hh)
{
    // hbuf[0..15]: hidden state; hbuf[16..31]: per-lane dummy slots so the STS
    // is 32 distinct addresses (no same-address store arbitration).
    __shared__ __align__(16) float hbuf[32];
    // Double-buffered x staging: xstage[buf][s] = x value for step s of a chunk.
    __shared__ __align__(16) float xstage[2][32];

    const int lane = threadIdx.x;
    const int j    = lane & 15;   // lanes j and j+16 do identical work

    // sigmoid(v) = 0.5 + 0.5*tanh(v/2): r/z rows pre-halved.
    // n: narg = xgn + D + t_r*D with D = 0.5*(w_n.h + b_n).
    unsigned long long wr[8], wz[8], wn[8];
    #pragma unroll
    for (int k = 0; k < 8; ++k) {
        const float* rr = &w_hh[j * HID];
        const float* rz = &w_hh[(HID + j) * HID];
        const float* rn = &w_hh[(2 * HID + j) * HID];
        wr[k] = pk2(0.5f * rr[2 * k], 0.5f * rr[2 * k + 1]);
        wz[k] = pk2(0.5f * rz[2 * k], 0.5f * rz[2 * k + 1]);
        wn[k] = pk2(0.5f * rn[2 * k], 0.5f * rn[2 * k + 1]);
    }
    const float wih_r2  = 0.5f * w_ih[j];
    const float bias_r2 = 0.5f * (b_ih[j] + b_hh[j]);
    const float wih_z2  = 0.5f * w_ih[HID + j];
    const float bias_z2 = 0.5f * (b_ih[HID + j] + b_hh[HID + j]);
    const float wih_n   = w_ih[2 * HID + j];
    const float bih_n   = b_ih[2 * HID + j];
    const unsigned long long bn2pk = pk2(0.5f * b_hh[2 * HID + j], 0.0f);
    const unsigned long long Z64 = 0ull;

    hbuf[lane] = 0.0f;
    __syncwarp();
    float h_own = 0.0f;

    const uint32_t sbase = smem_u32(&hbuf[0]);
    const uint32_t waddr = sbase + (uint32_t)(lane * 4);   // 32 distinct slots
    const uint32_t xs    = smem_u32(&xstage[0][0]);

    float4* histp = (float4*)&g_hist[lane * T_LEN];        // private row per lane
    float4 hacc;

    const int xoff = BATCH - 1;

    // ---- stage chunk 0 and prime the x pipeline (straight-line, in-order) ----
    {
        const float x0 = x[lane * BATCH + xoff];           // chunk 0
        asm volatile("st.shared.f32 [%0], %1;"
                     :: "r"(xs + (uint32_t)(lane * 4)), "f"(x0));
    }
    float xt_cur;
    asm volatile("ld.shared.f32 %0, [%1];" : "=f"(xt_cur) : "r"(xs));  // step 0 x
    // xg_stage holds chunk c+1's x values at the top of chunk c's body.
    float xg_stage = x[(32 + lane) * BATCH + xoff];        // chunk 1

    for (int c = 0; c < NCHUNK; ++c) {
        const uint32_t off     = (uint32_t)((c & 1) << 7);
        const uint32_t rd_base = xs + off;                 // this chunk's x
        const uint32_t wr_base = xs + (off ^ 128u);        // next chunk's x
        // pointer for chunk c+2's LDG (issued at step 16; clamped at the end)
        const int c2 = (c + 2 < NCHUNK) ? (c + 2) : (NCHUNK - 1);
        const float* xp2 = &x[(c2 * 32 + lane) * BATCH + xoff];

        #pragma unroll
        for (int s = 0; s < 32; ++s) {
            // critical h loads first (in-order smem pipeline behind last STS)
            unsigned long long h0, h1, h2, h3, h4, h5, h6, h7;
            asm volatile("ld.shared.v2.u64 {%0, %1}, [%2];" : "=l"(h0), "=l"(h1) : "r"(sbase));
            asm volatile("ld.shared.v2.u64 {%0, %1}, [%2];" : "=l"(h2), "=l"(h3) : "r"(sbase + 16));
            asm volatile("ld.shared.v2.u64 {%0, %1}, [%2];" : "=l"(h4), "=l"(h5) : "r"(sbase + 32));
            asm volatile("ld.shared.v2.u64 {%0, %1}, [%2];" : "=l"(h6), "=l"(h7) : "r"(sbase + 48));

            // x-gate seeds from register (loaded last step) — ready before h0
            const float xgr = fmaf(xt_cur, wih_r2, bias_r2);
            const float xgz = fmaf(xt_cur, wih_z2, bias_z2);
            const float xgn = fmaf(xt_cur, wih_n,  bih_n);
            const unsigned long long seed_r = pk2(xgr, 0.0f);
            const unsigned long long seed_z = pk2(xgz, 0.0f);

            unsigned long long ar0, ar1, az0, az1, an0, an1;
            ar0 = fma2(wr[0], h0, seed_r); ar1 = fma2(wr[1], h1, Z64);
            an0 = fma2(wn[0], h0, bn2pk);  an1 = fma2(wn[1], h1, Z64);
            az0 = fma2(wz[0], h0, seed_z); az1 = fma2(wz[1], h1, Z64);
            ar0 = fma2(wr[2], h2, ar0);    ar1 = fma2(wr[3], h3, ar1);
            an0 = fma2(wn[2], h2, an0);    an1 = fma2(wn[3], h3, an1);
            az0 = fma2(wz[2], h2, az0);    az1 = fma2(wz[3], h3, az1);
            ar0 = fma2(wr[4], h4, ar0);    ar1 = fma2(wr[5], h5, ar1);
            an0 = fma2(wn[4], h4, an0);    an1 = fma2(wn[5], h5, an1);
            az0 = fma2(wz[4], h4, az0);    az1 = fma2(wz[5], h5, az1);
            ar0 = fma2(wr[6], h6, ar0);    ar1 = fma2(wr[7], h7, ar1);
            an0 = fma2(wn[6], h6, an0);    an1 = fma2(wn[7], h7, an1);
            az0 = fma2(wz[6], h6, az0);    az1 = fma2(wz[7], h7, az1);

            float lo, hi;
            upk2(lo, hi, add2(ar0, ar1)); const float gr = lo + hi;   // includes xgr
            upk2(lo, hi, add2(an0, an1)); const float D  = lo + hi;   // 0.5*(w_n.h+b_n)
            upk2(lo, hi, add2(az0, az1)); const float gz = lo + hi;   // includes xgz

            const float t_r = tanhap(gr);
            const float t_z = tanhap(gz);
            const float xnD = xgn + D;                 // hidden under t_r MUFU
            const float zg  = fmaf(0.5f, t_z, 0.5f);
            const float omz = fmaf(-0.5f, t_z, 0.5f);
            const float zh  = zg * h_own;

            const float narg = fmaf(t_r, D, xnD);
            const float n    = tanhap(narg);
            const float hn   = fmaf(n, omz, zh);       // single FMA after tanh_n
            h_own = hn;

            asm volatile("st.shared.f32 [%0], %1;" :: "r"(waddr), "f"(hn));

            // ---- tail (dead window): x pipeline + history ----
            if (s == 4) {   // stage chunk c+1's x (LDG'd two chunks ago / pre-loop)
                asm volatile("st.shared.f32 [%0], %1;"
                             :: "r"(wr_base + (uint32_t)(lane * 4)), "f"(xg_stage));
            }
            if (s == 16) {  // fetch chunk c+2's x (used at s==4 of chunk c+1)
                xg_stage = *xp2;
            }
            // load next step's x (broadcast LDS.32, off-path)
            if (s < 31) {
                asm volatile("ld.shared.f32 %0, [%1];"
                             : "=f"(xt_cur) : "r"(rd_base + (uint32_t)((s + 1) * 4)));
            } else {        // step 0 of chunk c+1 (staged at s==4 above)
                asm volatile("ld.shared.f32 %0, [%1];"
                             : "=f"(xt_cur) : "r"(wr_base));
            }

            // batched history write (one STG.128 per 4 steps, 32 distinct rows)
            if ((s & 3) == 0) hacc.x = hn;
            else if ((s & 3) == 1) hacc.y = hn;
            else if ((s & 3) == 2) hacc.z = hn;
            else { hacc.w = hn; *histp = hacc; ++histp; }
        }
    }
}

// out[t][o] = h_t . fc_w[o] + fc_b[o]   (history rows 0..15 = hidden units)
__global__ void fc_kernel(const float* __restrict__ fc_w,
                          const float* __restrict__ fc_b,
                          float* __restrict__ out)
{
    const int i = blockIdx.x * blockDim.x + threadIdx.x;
    if (i >= T_LEN * NOUT) return;
    const int t = i / NOUT;
    const int o = i - t * NOUT;
    float acc = fc_b[o];
    #pragma unroll
    for (int k = 0; k < HID; ++k)
        acc = fmaf(g_hist[k * T_LEN + t], fc_w[o * HID + k], acc);
    out[i] = acc;
}

extern "C" void kernel_launch(void* const* d_in, const int* in_sizes, int n_in,
                              void* d_out, int out_size)
{
    const float* x    = (const float*)d_in[0];
    const float* w_ih = (const float*)d_in[1];
    const float* w_hh = (const float*)d_in[2];
    const float* b_ih = (const float*)d_in[3];
    const float* b_hh = (const float*)d_in[4];
    const float* fc_w = (const float*)d_in[5];
    const float* fc_b = (const float*)d_in[6];
    float* out = (float*)d_out;

    gru_seq_kernel<<<1, 32>>>(x, w_ih, w_hh, b_ih, b_hh);

    const int n = T_LEN * NOUT;
    fc_kernel<<<(n + 255) / 256, 256>>>(fc_w, fc_b, out);
}

// round 13
// speedup vs baseline: 1.1491x; 1.0067x over previous
#include <cuda_runtime.h>
#include <cstdint>

// T=8192, B=512, H=16, IN=1, OUT=5; output = FC(GRU hidden of batch index 511).
#define T_LEN 8192
#define BATCH 512
#define HID   16
#define NOUT  5

// Transposed history with one private row per LANE; rows 16..31 are redundant
// duplicates (lanes j and j+16 compute identical values). fc reads rows 0..15.
__device__ float g_hist[32 * T_LEN];

__device__ __forceinline__ float tanhap(float x) {
    float y; asm("tanh.approx.f32 %0, %1;" : "=f"(y) : "f"(x)); return y;
}
__device__ __forceinline__ unsigned long long pk2(float lo, float hi) {
    unsigned long long r; asm("mov.b64 %0, {%1, %2};" : "=l"(r) : "f"(lo), "f"(hi)); return r;
}
__device__ __forceinline__ void upk2(float& lo, float& hi, unsigned long long v) {
    asm("mov.b64 {%0, %1}, %2;" : "=f"(lo), "=f"(hi) : "l"(v));
}
__device__ __forceinline__ unsigned long long fma2(unsigned long long a, unsigned long long b,
                                                   unsigned long long c) {
    unsigned long long d;
    asm("fma.rn.f32x2 %0, %1, %2, %3;" : "=l"(d) : "l"(a), "l"(b), "l"(c));
    return d;
}
__device__ __forceinline__ unsigned long long add2(unsigned long long a, unsigned long long b) {
    unsigned long long d;
    asm("add.rn.f32x2 %0, %1, %2;" : "=l"(d) : "l"(a), "l"(b));
    return d;
}
__device__ __forceinline__ uint32_t smem_u32(const void* p) {
    uint32_t a;
    asm("{ .reg .u64 t; cvta.to.shared.u64 t, %1; cvt.u32.u64 %0, t; }" : "=r"(a) : "l"(p));
    return a;
}

__global__ void __launch_bounds__(32, 1)
gru_seq_kernel(const float* __restrict__ x,
               const float* __restrict__ w_ih,
               const float* __restrict__ w_hh,
               const float* __restrict__ b_ih,
               const float* __restrict__ b_hh)
{
    // Slots 0..15: hidden state (written by low lanes). Slots 16..31: dummy
    // targets for the high half-warp so the STS has 32 DISTINCT addresses
    // (no same-address write arbitration in front of the critical h-LDS).
    __shared__ __align__(16) float hbuf[32];
    const unsigned FULL = 0xffffffffu;
    const int lane = threadIdx.x;
    const int j    = lane & 15;   // lanes j and j+16 do identical work

    // sigmoid(v) = 0.5 + 0.5*tanh(v/2): r/z rows pre-halved.
    // n: narg = xgn + D + t_r*D with D = 0.5*(w_n.h + b_n).
    unsigned long long wr[8], wz[8], wn[8];
    #pragma unroll
    for (int k = 0; k < 8; ++k) {
        const float* rr = &w_hh[j * HID];
        const float* rz = &w_hh[(HID + j) * HID];
        const float* rn = &w_hh[(2 * HID + j) * HID];
        wr[k] = pk2(0.5f * rr[2 * k], 0.5f * rr[2 * k + 1]);
        wz[k] = pk2(0.5f * rz[2 * k], 0.5f * rz[2 * k + 1]);
        wn[k] = pk2(0.5f * rn[2 * k], 0.5f * rn[2 * k + 1]);
    }
    const float wih_r2  = 0.5f * w_ih[j];
    const float bias_r2 = 0.5f * (b_ih[j] + b_hh[j]);
    const float wih_z2  = 0.5f * w_ih[HID + j];
    const float bias_z2 = 0.5f * (b_ih[HID + j] + b_hh[HID + j]);
    const float wih_n   = w_ih[2 * HID + j];
    const float bih_n   = b_ih[2 * HID + j];
    const unsigned long long bn2pk = pk2(0.5f * b_hh[2 * HID + j], 0.0f);
    const unsigned long long Z64 = 0ull;

    hbuf[lane] = 0.0f;
    __syncwarp();
    float h_own = 0.0f;

    const uint32_t sbase = smem_u32(&hbuf[0]);
    const uint32_t waddr = sbase + (uint32_t)(lane * 4);   // 32 distinct slots

    float4* histp = (float4*)&g_hist[lane * T_LEN];        // private row per lane
    float4 hacc;

    const int xoff = BATCH - 1;
    float xv      = x[(0  + lane) * BATCH + xoff];
    float xv_next = x[(32 + lane) * BATCH + xoff];

    const int NCHUNK = T_LEN / 32;
    for (int c = 0; c < NCHUNK; ++c) {
        #pragma unroll
        for (int s = 0; s < 32; ++s) {
            // warp-synchronous single-buffer roundtrip (in-order smem pipeline)
            unsigned long long h0, h1, h2, h3, h4, h5, h6, h7;
            asm volatile("ld.shared.v2.u64 {%0, %1}, [%2];" : "=l"(h0), "=l"(h1) : "r"(sbase));
            asm volatile("ld.shared.v2.u64 {%0, %1}, [%2];" : "=l"(h2), "=l"(h3) : "r"(sbase + 16));
            asm volatile("ld.shared.v2.u64 {%0, %1}, [%2];" : "=l"(h4), "=l"(h5) : "r"(sbase + 32));
            asm volatile("ld.shared.v2.u64 {%0, %1}, [%2];" : "=l"(h6), "=l"(h7) : "r"(sbase + 48));

            // x-gate terms: ready well before LDS data
            const float xt  = __shfl_sync(FULL, xv, s);
            const float xgr = fmaf(xt, wih_r2, bias_r2);
            const float xgz = fmaf(xt, wih_z2, bias_z2);
            const float xgn = fmaf(xt, wih_n,  bih_n);
            const unsigned long long seed_r = pk2(xgr, 0.0f);
            const unsigned long long seed_z = pk2(xgz, 0.0f);

            unsigned long long ar0, ar1, az0, az1, an0, an1;
            ar0 = fma2(wr[0], h0, seed_r); ar1 = fma2(wr[1], h1, Z64);
            an0 = fma2(wn[0], h0, bn2pk);  an1 = fma2(wn[1], h1, Z64);
            az0 = fma2(wz[0], h0, seed_z); az1 = fma2(wz[1], h1, Z64);
            ar0 = fma2(wr[2], h2, ar0);    ar1 = fma2(wr[3], h3, ar1);
            an0 = fma2(wn[2], h2, an0);    an1 = fma2(wn[3], h3, an1);
            az0 = fma2(wz[2], h2, az0);    az1 = fma2(wz[3], h3, az1);
            ar0 = fma2(wr[4], h4, ar0);    ar1 = fma2(wr[5], h5, ar1);
            an0 = fma2(wn[4], h4, an0);    an1 = fma2(wn[5], h5, an1);
            az0 = fma2(wz[4], h4, az0);    az1 = fma2(wz[5], h5, az1);
            ar0 = fma2(wr[6], h6, ar0);    ar1 = fma2(wr[7], h7, ar1);
            an0 = fma2(wn[6], h6, an0);    an1 = fma2(wn[7], h7, an1);
            az0 = fma2(wz[6], h6, az0);    az1 = fma2(wz[7], h7, az1);

            float lo, hi;
            upk2(lo, hi, add2(ar0, ar1)); const float gr = lo + hi;   // includes xgr
            upk2(lo, hi, add2(an0, an1)); const float D  = lo + hi;   // 0.5*(w_n.h+b_n)
            upk2(lo, hi, add2(az0, az1)); const float gz = lo + hi;   // includes xgz

            const float t_r = tanhap(gr);
            const float t_z = tanhap(gz);
            const float xnD = xgn + D;                 // hidden under t_r MUFU
            const float zg  = fmaf(0.5f, t_z, 0.5f);
            const float omz = fmaf(-0.5f, t_z, 0.5f);
            const float zh  = zg * h_own;

            const float narg = fmaf(t_r, D, xnD);
            const float n    = tanhap(narg);
            const float hn   = fmaf(n, omz, zh);       // single FMA after tanh_n
            h_own = hn;

            asm volatile("st.shared.f32 [%0], %1;" :: "r"(waddr), "f"(hn));

            // batched history write (one STG.128 per 4 steps, 32 distinct rows)
            if ((s & 3) == 0) hacc.x = hn;
            else if ((s & 3) == 1) hacc.y = hn;
            else if ((s & 3) == 2) hacc.z = hn;
            else { hacc.w = hn; *histp = hacc; ++histp; }
        }
        xv = xv_next;
        const int nc = (c + 2 < NCHUNK) ? (c + 2) : (NCHUNK - 1);   // branch-free
        xv_next = x[(nc * 32 + lane) * BATCH + xoff];
    }
}

// out[t][o] = h_t . fc_w[o] + fc_b[o]   (history rows 0..15 = hidden units)
__global__ void fc_kernel(const float* __restrict__ fc_w,
                          const float* __restrict__ fc_b,
                          float* __restrict__ out)
{
    const int i = blockIdx.x * blockDim.x + threadIdx.x;
    if (i >= T_LEN * NOUT) return;
    const int t = i / NOUT;
    const int o = i - t * NOUT;
    float acc = fc_b[o];
    #pragma unroll
    for (int k = 0; k < HID; ++k)
        acc = fmaf(g_hist[k * T_LEN + t], fc_w[o * HID + k], acc);
    out[i] = acc;
}

extern "C" void kernel_launch(void* const* d_in, const int* in_sizes, int n_in,
                              void* d_out, int out_size)
{
    const float* x    = (const float*)d_in[0];
    const float* w_ih = (const float*)d_in[1];
    const float* w_hh = (const float*)d_in[2];
    const float* b_ih = (const float*)d_in[3];
    const float* b_hh = (const float*)d_in[4];
    const float* fc_w = (const float*)d_in[5];
    const float* fc_b = (const float*)d_in[6];
    float* out = (float*)d_out;

    gru_seq_kernel<<<1, 32>>>(x, w_ih, w_hh, b_ih, b_hh);

    const int n = T_LEN * NOUT;
    fc_kernel<<<(n + 255) / 256, 256>>>(fc_w, fc_b, out);
}

// round 14
// speedup vs baseline: 1.2342x; 1.0740x over previous
#include <cuda_runtime.h>
#include <cstdint>

// T=8192, B=512, H=16, IN=1, OUT=5; output = FC(GRU hidden of batch index 511).
#define T_LEN 8192
#define BATCH 512
#define HID   16
#define NOUT  5

// Transposed history with one private row per LANE; rows 16..31 are garbage
// (high half-warp computes the z-gate, not valid hidden states). fc reads 0..15.
__device__ float g_hist[32 * T_LEN];

__device__ __forceinline__ float tanhap(float x) {
    float y; asm("tanh.approx.f32 %0, %1;" : "=f"(y) : "f"(x)); return y;
}
__device__ __forceinline__ unsigned long long pk2(float lo, float hi) {
    unsigned long long r; asm("mov.b64 %0, {%1, %2};" : "=l"(r) : "f"(lo), "f"(hi)); return r;
}
__device__ __forceinline__ void upk2(float& lo, float& hi, unsigned long long v) {
    asm("mov.b64 {%0, %1}, %2;" : "=f"(lo), "=f"(hi) : "l"(v));
}
__device__ __forceinline__ unsigned long long fma2(unsigned long long a, unsigned long long b,
                                                   unsigned long long c) {
    unsigned long long d;
    asm("fma.rn.f32x2 %0, %1, %2, %3;" : "=l"(d) : "l"(a), "l"(b), "l"(c));
    return d;
}
__device__ __forceinline__ unsigned long long add2(unsigned long long a, unsigned long long b) {
    unsigned long long d;
    asm("add.rn.f32x2 %0, %1, %2;" : "=l"(d) : "l"(a), "l"(b));
    return d;
}
__device__ __forceinline__ uint32_t smem_u32(const void* p) {
    uint32_t a;
    asm("{ .reg .u64 t; cvta.to.shared.u64 t, %1; cvt.u32.u64 %0, t; }" : "=r"(a) : "l"(p));
    return a;
}

__global__ void __launch_bounds__(32, 1)
gru_seq_kernel(const float* __restrict__ x,
               const float* __restrict__ w_ih,
               const float* __restrict__ w_hh,
               const float* __restrict__ b_ih,
               const float* __restrict__ b_hh)
{
    // Slots 0..15: hidden state (low lanes). Slots 16..31: dummy sink for the
    // high half-warp's STS (32 distinct addresses, no predication).
    __shared__ __align__(16) float hbuf[32];
    const unsigned FULL = 0xffffffffu;
    const int lane = threadIdx.x;
    const int j    = lane & 15;

    // Lane split: dotA row = r-row j (lanes<16) / z-row j (lanes>=16).
    // sigmoid(v) = 0.5 + 0.5*tanh(v/2): gate rows pre-halved.
    // n-dot on ALL lanes (valid on low lanes; high lanes produce garbage n/hn).
    // narg = xgn + D + t_r*D with D = 0.5*(w_n.h + b_n).
    const int rowA = (lane < 16) ? j : (HID + j);

    unsigned long long wA[8], wn[8];
    #pragma unroll
    for (int k = 0; k < 8; ++k) {
        const float* ra = &w_hh[rowA * HID];
        const float* rn = &w_hh[(2 * HID + j) * HID];
        wA[k] = pk2(0.5f * ra[2 * k], 0.5f * ra[2 * k + 1]);
        wn[k] = pk2(0.5f * rn[2 * k], 0.5f * rn[2 * k + 1]);
    }
    const float wihA2  = 0.5f * w_ih[rowA];
    const float biasA2 = 0.5f * (b_ih[rowA] + b_hh[rowA]);
    const float wih_n  = w_ih[2 * HID + j];
    const float bih_n  = b_ih[2 * HID + j];
    const unsigned long long bn2pk = pk2(0.5f * b_hh[2 * HID + j], 0.0f);
    const unsigned long long Z64 = 0ull;

    hbuf[lane] = 0.0f;
    __syncwarp();
    float h_own = 0.0f;   // valid on low lanes only

    const uint32_t sbase = smem_u32(&hbuf[0]);
    const uint32_t waddr = sbase + (uint32_t)(lane * 4);   // 32 distinct slots

    float4* histp = (float4*)&g_hist[lane * T_LEN];
    float4 hacc;

    const int xoff = BATCH - 1;
    float xv      = x[(0  + lane) * BATCH + xoff];
    float xv_next = x[(32 + lane) * BATCH + xoff];

    const int NCHUNK = T_LEN / 32;
    for (int c = 0; c < NCHUNK; ++c) {
        #pragma unroll
        for (int s = 0; s < 32; ++s) {
            // warp-synchronous single-buffer roundtrip (in-order smem pipeline)
            unsigned long long h0, h1, h2, h3, h4, h5, h6, h7;
            asm volatile("ld.shared.v2.u64 {%0, %1}, [%2];" : "=l"(h0), "=l"(h1) : "r"(sbase));
            asm volatile("ld.shared.v2.u64 {%0, %1}, [%2];" : "=l"(h2), "=l"(h3) : "r"(sbase + 16));
            asm volatile("ld.shared.v2.u64 {%0, %1}, [%2];" : "=l"(h4), "=l"(h5) : "r"(sbase + 32));
            asm volatile("ld.shared.v2.u64 {%0, %1}, [%2];" : "=l"(h6), "=l"(h7) : "r"(sbase + 48));

            // x-gate terms: ready well before LDS data
            const float xt  = __shfl_sync(FULL, xv, s);
            const float xgA = fmaf(xt, wihA2, biasA2);
            const float xgn = fmaf(xt, wih_n,  bih_n);
            const unsigned long long seed_A = pk2(xgA, 0.0f);

            // two 16-dots: dotA (r|z by half), dotN. 16 fma2 total.
            unsigned long long aA0, aA1, aN0, aN1;
            aA0 = fma2(wA[0], h0, seed_A); aA1 = fma2(wA[1], h1, Z64);
            aN0 = fma2(wn[0], h0, bn2pk);  aN1 = fma2(wn[1], h1, Z64);
            aA0 = fma2(wA[2], h2, aA0);    aA1 = fma2(wA[3], h3, aA1);
            aN0 = fma2(wn[2], h2, aN0);    aN1 = fma2(wn[3], h3, aN1);
            aA0 = fma2(wA[4], h4, aA0);    aA1 = fma2(wA[5], h5, aA1);
            aN0 = fma2(wn[4], h4, aN0);    aN1 = fma2(wn[5], h5, aN1);
            aA0 = fma2(wA[6], h6, aA0);    aA1 = fma2(wA[7], h7, aA1);
            aN0 = fma2(wn[6], h6, aN0);    aN1 = fma2(wn[7], h7, aN1);

            float lo, hi;
            upk2(lo, hi, add2(aA0, aA1)); const float gA = lo + hi;   // includes xgA
            upk2(lo, hi, add2(aN0, aN1)); const float D  = lo + hi;   // 0.5*(w_n.h+b_n)

            // one MUFU covers both gates: low lanes -> t_r, high lanes -> t_z
            const float t  = tanhap(gA);
            const float tz = __shfl_xor_sync(FULL, t, 16);   // low lanes: t_z

            const float xnD  = xgn + D;
            const float narg = fmaf(t, D, xnD);              // t == t_r on low
            const float n    = tanhap(narg);

            const float zg  = fmaf(0.5f, tz, 0.5f);          // overlaps tanh_n
            const float omz = fmaf(-0.5f, tz, 0.5f);
            const float zh  = zg * h_own;

            const float hn  = fmaf(n, omz, zh);              // valid on low lanes
            h_own = hn;

            asm volatile("st.shared.f32 [%0], %1;" :: "r"(waddr), "f"(hn));

            // batched history write (one STG.128 per 4 steps, 32 distinct rows)
            if ((s & 3) == 0) hacc.x = hn;
            else if ((s & 3) == 1) hacc.y = hn;
            else if ((s & 3) == 2) hacc.z = hn;
            else { hacc.w = hn; *histp = hacc; ++histp; }
        }
        xv = xv_next;
        const int nc = (c + 2 < NCHUNK) ? (c + 2) : (NCHUNK - 1);   // branch-free
        xv_next = x[(nc * 32 + lane) * BATCH + xoff];
    }
}

// out[t][o] = h_t . fc_w[o] + fc_b[o]   (history rows 0..15 = hidden units)
__global__ void fc_kernel(const float* __restrict__ fc_w,
                          const float* __restrict__ fc_b,
                          float* __restrict__ out)
{
    const int i = blockIdx.x * blockDim.x + threadIdx.x;
    if (i >= T_LEN * NOUT) return;
    const int t = i / NOUT;
    const int o = i - t * NOUT;
    float acc = fc_b[o];
    #pragma unroll
    for (int k = 0; k < HID; ++k)
        acc = fmaf(g_hist[k * T_LEN + t], fc_w[o * HID + k], acc);
    out[i] = acc;
}

extern "C" void kernel_launch(void* const* d_in, const int* in_sizes, int n_in,
                              void* d_out, int out_size)
{
    const float* x    = (const float*)d_in[0];
    const float* w_ih = (const float*)d_in[1];
    const float* w_hh = (const float*)d_in[2];
    const float* b_ih = (const float*)d_in[3];
    const float* b_hh = (const float*)d_in[4];
    const float* fc_w = (const float*)d_in[5];
    const float* fc_b = (const float*)d_in[6];
    float* out = (float*)d_out;

    gru_seq_kernel<<<1, 32>>>(x, w_ih, w_hh, b_ih, b_hh);

    const int n = T_LEN * NOUT;
    fc_kernel<<<(n + 255) / 256, 256>>>(fc_w, fc_b, out);
}

// round 15
// speedup vs baseline: 1.2483x; 1.0114x over previous
#include <cuda_runtime.h>
#include <cstdint>

// T=8192, B=512, H=16, IN=1, OUT=5; output = FC(GRU hidden of batch index 511).
#define T_LEN 8192
#define BATCH 512
#define HID   16
#define NOUT  5

// Transposed history with one private row per LANE; rows 16..31 are garbage
// (high half-warp computes the z-gate, not valid hidden states). fc reads 0..15.
__device__ float g_hist[32 * T_LEN];

__device__ __forceinline__ float tanhap(float x) {
    float y; asm("tanh.approx.f32 %0, %1;" : "=f"(y) : "f"(x)); return y;
}
__device__ __forceinline__ unsigned long long pk2(float lo, float hi) {
    unsigned long long r; asm("mov.b64 %0, {%1, %2};" : "=l"(r) : "f"(lo), "f"(hi)); return r;
}
__device__ __forceinline__ void upk2(float& lo, float& hi, unsigned long long v) {
    asm("mov.b64 {%0, %1}, %2;" : "=f"(lo), "=f"(hi) : "l"(v));
}
__device__ __forceinline__ unsigned long long fma2(unsigned long long a, unsigned long long b,
                                                   unsigned long long c) {
    unsigned long long d;
    asm("fma.rn.f32x2 %0, %1, %2, %3;" : "=l"(d) : "l"(a), "l"(b), "l"(c));
    return d;
}
__device__ __forceinline__ unsigned long long add2(unsigned long long a, unsigned long long b) {
    unsigned long long d;
    asm("add.rn.f32x2 %0, %1, %2;" : "=l"(d) : "l"(a), "l"(b));
    return d;
}
__device__ __forceinline__ uint32_t smem_u32(const void* p) {
    uint32_t a;
    asm("{ .reg .u64 t; cvta.to.shared.u64 t, %1; cvt.u32.u64 %0, t; }" : "=r"(a) : "l"(p));
    return a;
}

__global__ void __launch_bounds__(32, 1)
gru_seq_kernel(const float* __restrict__ x,
               const float* __restrict__ w_ih,
               const float* __restrict__ w_hh,
               const float* __restrict__ b_ih,
               const float* __restrict__ b_hh)
{
    // Slots 0..15: hidden state (low lanes). Slots 16..31: dummy sink for the
    // high half-warp's STS (32 distinct addresses, no predication).
    __shared__ __align__(16) float hbuf[32];
    const unsigned FULL = 0xffffffffu;
    const int lane = threadIdx.x;
    const int j    = lane & 15;

    // Lane split: dotA row = r-row j (lanes<16) / z-row j (lanes>=16).
    // sigmoid(v) = 0.5 + 0.5*tanh(v/2): gate rows pre-halved.
    // n-dot on ALL lanes (valid on low lanes; high lanes produce garbage n/hn).
    // narg = xgn + D + t_r*D with D = 0.5*(w_n.h + b_n).
    // Tail: hn = 0.5*(n + h) + tz*0.5*(h - n) = P + tz*Q with
    //   hh = 0.5*h_own (precomputed in dead window), P = hh + 0.5n, Q = hh - 0.5n.
    const int rowA = (lane < 16) ? j : (HID + j);

    unsigned long long wA[8], wn[8];
    #pragma unroll
    for (int k = 0; k < 8; ++k) {
        const float* ra = &w_hh[rowA * HID];
        const float* rn = &w_hh[(2 * HID + j) * HID];
        wA[k] = pk2(0.5f * ra[2 * k], 0.5f * ra[2 * k + 1]);
        wn[k] = pk2(0.5f * rn[2 * k], 0.5f * rn[2 * k + 1]);
    }
    const float wihA2  = 0.5f * w_ih[rowA];
    const float biasA2 = 0.5f * (b_ih[rowA] + b_hh[rowA]);
    const float wih_n  = w_ih[2 * HID + j];
    const float bih_n  = b_ih[2 * HID + j];
    const unsigned long long bn2pk = pk2(0.5f * b_hh[2 * HID + j], 0.0f);
    const unsigned long long Z64 = 0ull;

    hbuf[lane] = 0.0f;
    __syncwarp();
    float hh = 0.0f;   // 0.5 * h_own, maintained in the dead window

    const uint32_t sbase = smem_u32(&hbuf[0]);
    const uint32_t waddr = sbase + (uint32_t)(lane * 4);   // 32 distinct slots

    float4* histp = (float4*)&g_hist[lane * T_LEN];
    float4 hacc;

    const int xoff = BATCH - 1;
    float xv      = x[(0  + lane) * BATCH + xoff];
    float xv_next = x[(32 + lane) * BATCH + xoff];

    const int NCHUNK = T_LEN / 32;
    for (int c = 0; c < NCHUNK; ++c) {
        #pragma unroll
        for (int s = 0; s < 32; ++s) {
            // warp-synchronous single-buffer roundtrip (in-order smem pipeline)
            unsigned long long h0, h1, h2, h3, h4, h5, h6, h7;
            asm volatile("ld.shared.v2.u64 {%0, %1}, [%2];" : "=l"(h0), "=l"(h1) : "r"(sbase));
            asm volatile("ld.shared.v2.u64 {%0, %1}, [%2];" : "=l"(h2), "=l"(h3) : "r"(sbase + 16));
            asm volatile("ld.shared.v2.u64 {%0, %1}, [%2];" : "=l"(h4), "=l"(h5) : "r"(sbase + 32));
            asm volatile("ld.shared.v2.u64 {%0, %1}, [%2];" : "=l"(h6), "=l"(h7) : "r"(sbase + 48));

            // x-gate terms: ready well before LDS data
            const float xt  = __shfl_sync(FULL, xv, s);
            const float xgA = fmaf(xt, wihA2, biasA2);
            const float xgn = fmaf(xt, wih_n,  bih_n);
            const unsigned long long seed_A = pk2(xgA, 0.0f);

            // two 16-dots: dotA (r|z by half), dotN. 16 fma2 total.
            unsigned long long aA0, aA1, aN0, aN1;
            aA0 = fma2(wA[0], h0, seed_A); aA1 = fma2(wA[1], h1, Z64);
            aN0 = fma2(wn[0], h0, bn2pk);  aN1 = fma2(wn[1], h1, Z64);
            aA0 = fma2(wA[2], h2, aA0);    aA1 = fma2(wA[3], h3, aA1);
            aN0 = fma2(wn[2], h2, aN0);    aN1 = fma2(wn[3], h3, aN1);
            aA0 = fma2(wA[4], h4, aA0);    aA1 = fma2(wA[5], h5, aA1);
            aN0 = fma2(wn[4], h4, aN0);    aN1 = fma2(wn[5], h5, aN1);
            aA0 = fma2(wA[6], h6, aA0);    aA1 = fma2(wA[7], h7, aA1);
            aN0 = fma2(wn[6], h6, aN0);    aN1 = fma2(wn[7], h7, aN1);

            float lo, hi;
            upk2(lo, hi, add2(aA0, aA1)); const float gA = lo + hi;   // includes xgA
            upk2(lo, hi, add2(aN0, aN1)); const float D  = lo + hi;   // 0.5*(w_n.h+b_n)

            // one MUFU covers both gates: low lanes -> t_r, high lanes -> t_z
            const float t  = tanhap(gA);
            const float tz = __shfl_xor_sync(FULL, t, 16);   // low lanes: t_z

            const float xnD  = xgn + D;
            const float narg = fmaf(t, D, xnD);              // t == t_r on low
            const float n    = tanhap(narg);

            // re-associated tail: one fma after tanh_n / one after the shfl
            const float P  = fmaf( 0.5f, n, hh);             // 0.5*(n + h_own)
            const float Q  = fmaf(-0.5f, n, hh);             // 0.5*(h_own - n)
            const float hn = fmaf(tz, Q, P);                 // valid on low lanes

            asm volatile("st.shared.f32 [%0], %1;" :: "r"(waddr), "f"(hn));
            hh = 0.5f * hn;                                  // dead-window op

            // batched history write (one STG.128 per 4 steps, 32 distinct rows)
            if ((s & 3) == 0) hacc.x = hn;
            else if ((s & 3) == 1) hacc.y = hn;
            else if ((s & 3) == 2) hacc.z = hn;
            else { hacc.w = hn; *histp = hacc; ++histp; }
        }
        xv = xv_next;
        const int nc = (c + 2 < NCHUNK) ? (c + 2) : (NCHUNK - 1);   // branch-free
        xv_next = x[(nc * 32 + lane) * BATCH + xoff];
    }
}

// out[t][o] = h_t . fc_w[o] + fc_b[o]   (history rows 0..15 = hidden units)
__global__ void fc_kernel(const float* __restrict__ fc_w,
                          const float* __restrict__ fc_b,
                          float* __restrict__ out)
{
    const int i = blockIdx.x * blockDim.x + threadIdx.x;
    if (i >= T_LEN * NOUT) return;
    const int t = i / NOUT;
    const int o = i - t * NOUT;
    float acc = fc_b[o];
    #pragma unroll
    for (int k = 0; k < HID; ++k)
        acc = fmaf(g_hist[k * T_LEN + t], fc_w[o * HID + k], acc);
    out[i] = acc;
}

extern "C" void kernel_launch(void* const* d_in, const int* in_sizes, int n_in,
                              void* d_out, int out_size)
{
    const float* x    = (const float*)d_in[0];
    const float* w_ih = (const float*)d_in[1];
    const float* w_hh = (const float*)d_in[2];
    const float* b_ih = (const float*)d_in[3];
    const float* b_hh = (const float*)d_in[4];
    const float* fc_w = (const float*)d_in[5];
    const float* fc_b = (const float*)d_in[6];
    float* out = (float*)d_out;

    gru_seq_kernel<<<1, 32>>>(x, w_ih, w_hh, b_ih, b_hh);

    const int n = T_LEN * NOUT;
    fc_kernel<<<(n + 255) / 256, 256>>>(fc_w, fc_b, out);
}